// round 1
// baseline (speedup 1.0000x reference)
#include <cuda_runtime.h>
#include <math.h>

#define D_MODEL 1024
#define NHEAD 16
#define HEAD_DIM 64
#define BATCH 2
#define SEQ 2048
#define MTOT (BATCH*SEQ)   // 4096

// Scratch (allocation-free rule: __device__ globals)
__device__ float g_Q[MTOT * D_MODEL];
__device__ float g_K[MTOT * D_MODEL];
__device__ float g_V[MTOT * D_MODEL];
__device__ float g_Attn[MTOT * D_MODEL];

// ---------------------------------------------------------------------------
// C[M,N] = A[M,K] @ W[N,K]^T + bias[N]    (M=4096, N=K=1024 fixed)
// 128x128 block tile, BK=8, 256 threads, 8x8 per-thread microtile.
// ---------------------------------------------------------------------------
__global__ __launch_bounds__(256) void gemm_nt(
    const float* __restrict__ A, const float* __restrict__ W,
    const float* __restrict__ bias, float* __restrict__ C)
{
    const int K = D_MODEL;
    const int N = D_MODEL;
    __shared__ float As[8][128];
    __shared__ float Ws[8][128];

    const int m0 = blockIdx.y * 128;
    const int n0 = blockIdx.x * 128;
    const int t  = threadIdx.x;
    const int tx = t & 15;        // 0..15 -> N direction
    const int ty = t >> 4;        // 0..15 -> M direction
    const int lrow = t >> 1;      // 0..127
    const int lseg = (t & 1) << 2;// 0 or 4

    float acc[8][8];
    #pragma unroll
    for (int i = 0; i < 8; i++)
        #pragma unroll
        for (int j = 0; j < 8; j++) acc[i][j] = 0.f;

    const float* Aptr = A + (m0 + lrow) * K + lseg;
    const float* Wptr = W + (n0 + lrow) * K + lseg;

    for (int k0 = 0; k0 < K; k0 += 8) {
        float4 av = *(const float4*)(Aptr + k0);
        float4 wv = *(const float4*)(Wptr + k0);
        As[lseg + 0][lrow] = av.x; As[lseg + 1][lrow] = av.y;
        As[lseg + 2][lrow] = av.z; As[lseg + 3][lrow] = av.w;
        Ws[lseg + 0][lrow] = wv.x; Ws[lseg + 1][lrow] = wv.y;
        Ws[lseg + 2][lrow] = wv.z; Ws[lseg + 3][lrow] = wv.w;
        __syncthreads();

        #pragma unroll
        for (int k = 0; k < 8; k++) {
            float a[8], b[8];
            #pragma unroll
            for (int i = 0; i < 8; i++) a[i] = As[k][ty * 8 + i];
            #pragma unroll
            for (int j = 0; j < 8; j++) b[j] = Ws[k][tx * 8 + j];
            #pragma unroll
            for (int i = 0; i < 8; i++)
                #pragma unroll
                for (int j = 0; j < 8; j++)
                    acc[i][j] = fmaf(a[i], b[j], acc[i][j]);
        }
        __syncthreads();
    }

    #pragma unroll
    for (int i = 0; i < 8; i++) {
        const int m = m0 + ty * 8 + i;
        #pragma unroll
        for (int j = 0; j < 8; j += 4) {
            const int n = n0 + tx * 8 + j;
            float4 o;
            o.x = acc[i][j + 0] + bias[n + 0];
            o.y = acc[i][j + 1] + bias[n + 1];
            o.z = acc[i][j + 2] + bias[n + 2];
            o.w = acc[i][j + 3] + bias[n + 3];
            *(float4*)&C[m * N + n] = o;
        }
    }
}

// ---------------------------------------------------------------------------
// Flash attention fp32. One block per (q-tile of 64 rows, head, batch).
// 256 threads as 16x16 grid: thread (ty,tx) owns rows ty*4..+3, cols tx*4..+3
// of the 64x64 S tile and of the 64x64 O accumulator.
// Shared: Qs[64][65], KPs[64][65] (K tile, then reused for P), Vs[64][65].
// ---------------------------------------------------------------------------
#define AP 65
#define ATTN_SMEM (3 * 64 * AP * (int)sizeof(float))   // 49920 bytes

__global__ __launch_bounds__(256) void attn_kernel(
    const float* __restrict__ Qb, const float* __restrict__ Kb,
    const float* __restrict__ Vb, float* __restrict__ Ob)
{
    extern __shared__ float sm[];
    float* Qs  = sm;
    float* KPs = sm + 64 * AP;
    float* Vs  = sm + 2 * 64 * AP;

    const int qt = blockIdx.x;
    const int h  = blockIdx.y;
    const int b  = blockIdx.z;
    const int t  = threadIdx.x;
    const int tx = t & 15;
    const int ty = t >> 4;
    const float scale = 0.125f;   // 1/sqrt(64)

    const int base_q = b * SEQ + qt * 64;

    // Load Q tile (scale folded in). 64x64 floats = 1024 float4s.
    #pragma unroll
    for (int i = 0; i < 4; i++) {
        int idx = t + i * 256;
        int r = idx >> 4;
        int c = (idx & 15) << 2;
        float4 v = *(const float4*)&Qb[(base_q + r) * D_MODEL + h * HEAD_DIM + c];
        Qs[r * AP + c + 0] = v.x * scale;
        Qs[r * AP + c + 1] = v.y * scale;
        Qs[r * AP + c + 2] = v.z * scale;
        Qs[r * AP + c + 3] = v.w * scale;
    }

    float m_i[4], l_i[4], o[4][4];
    #pragma unroll
    for (int i = 0; i < 4; i++) {
        m_i[i] = -INFINITY;
        l_i[i] = 0.f;
        #pragma unroll
        for (int j = 0; j < 4; j++) o[i][j] = 0.f;
    }

    for (int jt = 0; jt < SEQ / 64; jt++) {
        const int base_k = b * SEQ + jt * 64;
        #pragma unroll
        for (int i = 0; i < 4; i++) {
            int idx = t + i * 256;
            int r = idx >> 4;
            int c = (idx & 15) << 2;
            int g = (base_k + r) * D_MODEL + h * HEAD_DIM + c;
            float4 kv = *(const float4*)&Kb[g];
            float4 vv = *(const float4*)&Vb[g];
            KPs[r * AP + c + 0] = kv.x; KPs[r * AP + c + 1] = kv.y;
            KPs[r * AP + c + 2] = kv.z; KPs[r * AP + c + 3] = kv.w;
            Vs[r * AP + c + 0] = vv.x; Vs[r * AP + c + 1] = vv.y;
            Vs[r * AP + c + 2] = vv.z; Vs[r * AP + c + 3] = vv.w;
        }
        __syncthreads();   // also covers Qs on first iteration

        // S = (Q*scale) @ K^T  (4x4 fragment per thread)
        float s[4][4];
        #pragma unroll
        for (int i = 0; i < 4; i++)
            #pragma unroll
            for (int j = 0; j < 4; j++) s[i][j] = 0.f;

        #pragma unroll 4
        for (int d = 0; d < 64; d++) {
            float a[4], bb[4];
            #pragma unroll
            for (int i = 0; i < 4; i++) a[i]  = Qs[(ty * 4 + i) * AP + d];
            #pragma unroll
            for (int j = 0; j < 4; j++) bb[j] = KPs[(tx * 4 + j) * AP + d];
            #pragma unroll
            for (int i = 0; i < 4; i++)
                #pragma unroll
                for (int j = 0; j < 4; j++)
                    s[i][j] = fmaf(a[i], bb[j], s[i][j]);
        }
        __syncthreads();   // everyone done reading K tile (KPs gets reused for P)

        // Online softmax per row (16 tx-threads per row, width-16 shuffles).
        #pragma unroll
        for (int i = 0; i < 4; i++) {
            float mt = fmaxf(fmaxf(s[i][0], s[i][1]), fmaxf(s[i][2], s[i][3]));
            #pragma unroll
            for (int off = 8; off > 0; off >>= 1)
                mt = fmaxf(mt, __shfl_xor_sync(0xffffffffu, mt, off, 16));
            float mn = fmaxf(m_i[i], mt);
            float alpha = __expf(m_i[i] - mn);
            m_i[i] = mn;
            float rs = 0.f;
            #pragma unroll
            for (int j = 0; j < 4; j++) {
                s[i][j] = __expf(s[i][j] - mn);
                rs += s[i][j];
            }
            #pragma unroll
            for (int off = 8; off > 0; off >>= 1)
                rs += __shfl_xor_sync(0xffffffffu, rs, off, 16);
            l_i[i] = l_i[i] * alpha + rs;
            #pragma unroll
            for (int j = 0; j < 4; j++) o[i][j] *= alpha;
        }

        // Stage P into shared (reusing K buffer).
        #pragma unroll
        for (int i = 0; i < 4; i++)
            #pragma unroll
            for (int j = 0; j < 4; j++)
                KPs[(ty * 4 + i) * AP + tx * 4 + j] = s[i][j];
        __syncthreads();

        // O += P @ V
        #pragma unroll 4
        for (int jj = 0; jj < 64; jj++) {
            float a[4], bb[4];
            #pragma unroll
            for (int i = 0; i < 4; i++) a[i]  = KPs[(ty * 4 + i) * AP + jj];
            #pragma unroll
            for (int c = 0; c < 4; c++) bb[c] = Vs[jj * AP + tx * 4 + c];
            #pragma unroll
            for (int i = 0; i < 4; i++)
                #pragma unroll
                for (int c = 0; c < 4; c++)
                    o[i][c] = fmaf(a[i], bb[c], o[i][c]);
        }
        __syncthreads();   // before next tile overwrites KPs/Vs
    }

    // Normalize and write out in [B, T, H*hd] layout (un-transposed for Wo GEMM).
    #pragma unroll
    for (int i = 0; i < 4; i++) {
        float inv = 1.f / l_i[i];
        int q = base_q + ty * 4 + i;
        #pragma unroll
        for (int c = 0; c < 4; c++)
            Ob[q * D_MODEL + h * HEAD_DIM + tx * 4 + c] = o[i][c] * inv;
    }
}

// ---------------------------------------------------------------------------
extern "C" void kernel_launch(void* const* d_in, const int* in_sizes, int n_in,
                              void* d_out, int out_size)
{
    const float* query = (const float*)d_in[0];
    const float* key   = (const float*)d_in[1];
    const float* value = (const float*)d_in[2];
    const float* Wq    = (const float*)d_in[3];
    const float* bq    = (const float*)d_in[4];
    const float* Wk    = (const float*)d_in[5];
    const float* bk    = (const float*)d_in[6];
    const float* Wv    = (const float*)d_in[7];
    const float* bv    = (const float*)d_in[8];
    const float* Wo    = (const float*)d_in[9];
    const float* bo    = (const float*)d_in[10];
    float* out = (float*)d_out;

    float *pQ, *pK, *pV, *pA;
    cudaGetSymbolAddress((void**)&pQ, g_Q);
    cudaGetSymbolAddress((void**)&pK, g_K);
    cudaGetSymbolAddress((void**)&pV, g_V);
    cudaGetSymbolAddress((void**)&pA, g_Attn);

    cudaFuncSetAttribute(attn_kernel,
                         cudaFuncAttributeMaxDynamicSharedMemorySize, ATTN_SMEM);

    dim3 gemm_grid(D_MODEL / 128, MTOT / 128);   // (8, 32)

    // Projections
    gemm_nt<<<gemm_grid, 256>>>(query, Wq, bq, pQ);
    gemm_nt<<<gemm_grid, 256>>>(key,   Wk, bk, pK);
    gemm_nt<<<gemm_grid, 256>>>(value, Wv, bv, pV);

    // Attention
    dim3 attn_grid(SEQ / 64, NHEAD, BATCH);      // (32, 16, 2)
    attn_kernel<<<attn_grid, 256, ATTN_SMEM>>>(pQ, pK, pV, pA);

    // Output projection
    gemm_nt<<<gemm_grid, 256>>>(pA, Wo, bo, out);
}

// round 2
// speedup vs baseline: 1.0928x; 1.0928x over previous
#include <cuda_runtime.h>
#include <mma.h>
#include <math.h>

using namespace nvcuda;

#define D_MODEL 1024
#define NHEAD 16
#define HEAD_DIM 64
#define BATCH 2
#define SEQ 2048
#define MTOT (BATCH*SEQ)   // 4096

// Scratch (allocation-free rule: __device__ globals)
__device__ float g_Q[MTOT * D_MODEL];
__device__ float g_K[MTOT * D_MODEL];
__device__ float g_V[MTOT * D_MODEL];
__device__ float g_Attn[MTOT * D_MODEL];

// ---------------------------------------------------------------------------
// tf32 GEMM: C[M,N] = A[M,K] @ W[N,K]^T   (no bias; M=4096, N=K=1024)
// 128x128 block, BK=32, 8 warps (2x4), warp tile 64x32, wmma m16n16k8 tf32.
// ---------------------------------------------------------------------------
#define GS 40   // smem stride (floats) for 32-wide K panel

__global__ __launch_bounds__(256) void gemm_tf32(
    const float* __restrict__ A, const float* __restrict__ W,
    float* __restrict__ C)
{
    __shared__ float As[128 * GS];
    __shared__ float Ws[128 * GS];

    const int m0 = blockIdx.y * 128;
    const int n0 = blockIdx.x * 128;
    const int t  = threadIdx.x;
    const int wid = t >> 5;
    const int wm = wid >> 2;      // 0..1  -> m offset wm*64
    const int wn = wid & 3;       // 0..3  -> n offset wn*32
    const int lrow = t >> 1;      // 0..127
    const int lcol = (t & 1) * 16;

    wmma::fragment<wmma::accumulator, 16, 16, 8, float> acc[4][2];
    #pragma unroll
    for (int i = 0; i < 4; i++)
        #pragma unroll
        for (int j = 0; j < 2; j++) wmma::fill_fragment(acc[i][j], 0.f);

    const float* Ap = A + (m0 + lrow) * D_MODEL + lcol;
    const float* Wp = W + (n0 + lrow) * D_MODEL + lcol;

    float4 ra[4], rw[4];
    #pragma unroll
    for (int i = 0; i < 4; i++) {
        ra[i] = *(const float4*)(Ap + i * 4);
        rw[i] = *(const float4*)(Wp + i * 4);
    }

    for (int k0 = 0; k0 < D_MODEL; k0 += 32) {
        #pragma unroll
        for (int i = 0; i < 4; i++) {
            *(float4*)&As[lrow * GS + lcol + i * 4] = ra[i];
            *(float4*)&Ws[lrow * GS + lcol + i * 4] = rw[i];
        }
        __syncthreads();

        if (k0 + 32 < D_MODEL) {
            #pragma unroll
            for (int i = 0; i < 4; i++) {
                ra[i] = *(const float4*)(Ap + k0 + 32 + i * 4);
                rw[i] = *(const float4*)(Wp + k0 + 32 + i * 4);
            }
        }

        #pragma unroll
        for (int kk = 0; kk < 4; kk++) {
            wmma::fragment<wmma::matrix_a, 16, 16, 8, wmma::precision::tf32, wmma::row_major> af[4];
            wmma::fragment<wmma::matrix_b, 16, 16, 8, wmma::precision::tf32, wmma::col_major> bf[2];
            #pragma unroll
            for (int i = 0; i < 4; i++) {
                wmma::load_matrix_sync(af[i], &As[(wm * 64 + i * 16) * GS + kk * 8], GS);
                #pragma unroll
                for (int e = 0; e < af[i].num_elements; e++)
                    af[i].x[e] = wmma::__float_to_tf32(af[i].x[e]);
            }
            #pragma unroll
            for (int j = 0; j < 2; j++) {
                wmma::load_matrix_sync(bf[j], &Ws[(wn * 32 + j * 16) * GS + kk * 8], GS);
                #pragma unroll
                for (int e = 0; e < bf[j].num_elements; e++)
                    bf[j].x[e] = wmma::__float_to_tf32(bf[j].x[e]);
            }
            #pragma unroll
            for (int i = 0; i < 4; i++)
                #pragma unroll
                for (int j = 0; j < 2; j++)
                    wmma::mma_sync(acc[i][j], af[i], bf[j], acc[i][j]);
        }
        __syncthreads();
    }

    #pragma unroll
    for (int i = 0; i < 4; i++)
        #pragma unroll
        for (int j = 0; j < 2; j++)
            wmma::store_matrix_sync(
                &C[(m0 + wm * 64 + i * 16) * D_MODEL + n0 + wn * 32 + j * 16],
                acc[i][j], D_MODEL, wmma::mem_row_major);
}

// ---------------------------------------------------------------------------
// Flash attention, tf32 wmma. Block = (q-tile 128, head, batch), 8 warps.
// Warp w owns the 16-row strip w*16..w*16+15 of S / O.
// Thread t handles softmax/O-update for row t>>1, cols (t&1)*32..+31.
// ---------------------------------------------------------------------------
#define AS 72   // smem stride (floats) for 64-wide panels
#define QT 128
#define KT 64
#define ATTN_SMEM ((QT*AS*3 + KT*AS*2 + 128) * (int)sizeof(float))

__global__ __launch_bounds__(256) void attn_tf32(
    const float* __restrict__ Qb, const float* __restrict__ Kb,
    const float* __restrict__ Vb, float* __restrict__ Ob,
    const float* __restrict__ bq, const float* __restrict__ bk,
    const float* __restrict__ bv)
{
    extern __shared__ float sm[];
    float* Qs  = sm;                    // [128][72]
    float* Ss  = Qs  + QT * AS;         // [128][72]  S, then P, then PV
    float* Os  = Ss  + QT * AS;         // [128][72]
    float* Ks  = Os  + QT * AS;         // [64][72]
    float* Vts = Ks  + KT * AS;         // [64][72]  V transposed: [d][key]
    float* bks = Vts + KT * AS;         // [64]
    float* bvs = bks + 64;              // [64]

    const int qt = blockIdx.x;
    const int h  = blockIdx.y;
    const int b  = blockIdx.z;
    const int t  = threadIdx.x;
    const int w  = t >> 5;
    const int srow = t >> 1;            // softmax / O-update row
    const int scol = (t & 1) * 32;
    const float scale = 0.125f;

    const int base_q = b * SEQ + qt * QT;
    const int hcol = h * HEAD_DIM;

    // bias to smem
    if (t < 64) { bks[t] = bk[hcol + t]; bvs[t] = bv[hcol + t]; }

    // load Q (bias + scale folded), zero O
    #pragma unroll
    for (int i = 0; i < 8; i++) {
        const int c = scol + i * 4;
        float4 v = *(const float4*)&Qb[(base_q + srow) * D_MODEL + hcol + c];
        float4 bb = *(const float4*)&bq[hcol + c];
        Qs[srow * AS + c + 0] = (v.x + bb.x) * scale;
        Qs[srow * AS + c + 1] = (v.y + bb.y) * scale;
        Qs[srow * AS + c + 2] = (v.z + bb.z) * scale;
        Qs[srow * AS + c + 3] = (v.w + bb.w) * scale;
        *(float4*)&Os[srow * AS + c] = make_float4(0.f, 0.f, 0.f, 0.f);
    }

    float m_i = -1e30f, l_i = 0.f;

    // K/V prefetch (tile 0)
    const int kr = t >> 2;              // 0..63
    const int kc = (t & 3) * 16;
    float4 rk[4], rv[4];
    {
        const int g = (b * SEQ + kr) * D_MODEL + hcol + kc;
        #pragma unroll
        for (int i = 0; i < 4; i++) {
            rk[i] = *(const float4*)&Kb[g + i * 4];
            rv[i] = *(const float4*)&Vb[g + i * 4];
        }
    }
    __syncthreads();   // bias smem ready

    for (int jt = 0; jt < SEQ / KT; jt++) {
        // stage K (row-major) and V (transposed) with bias
        #pragma unroll
        for (int i = 0; i < 4; i++) {
            const int c = kc + i * 4;
            float4 bkv = *(const float4*)&bks[c];
            float4 bvv = *(const float4*)&bvs[c];
            float4 kv = rk[i], vv = rv[i];
            Ks[kr * AS + c + 0] = kv.x + bkv.x;
            Ks[kr * AS + c + 1] = kv.y + bkv.y;
            Ks[kr * AS + c + 2] = kv.z + bkv.z;
            Ks[kr * AS + c + 3] = kv.w + bkv.w;
            Vts[(c + 0) * AS + kr] = vv.x + bvv.x;
            Vts[(c + 1) * AS + kr] = vv.y + bvv.y;
            Vts[(c + 2) * AS + kr] = vv.z + bvv.z;
            Vts[(c + 3) * AS + kr] = vv.w + bvv.w;
        }
        __syncthreads();   // (A)

        if (jt + 1 < SEQ / KT) {
            const int g = (b * SEQ + (jt + 1) * KT + kr) * D_MODEL + hcol + kc;
            #pragma unroll
            for (int i = 0; i < 4; i++) {
                rk[i] = *(const float4*)&Kb[g + i * 4];
                rv[i] = *(const float4*)&Vb[g + i * 4];
            }
        }

        // S = Q @ K^T  (warp strip 16x64)
        {
            wmma::fragment<wmma::accumulator, 16, 16, 8, float> cS[4];
            #pragma unroll
            for (int n = 0; n < 4; n++) wmma::fill_fragment(cS[n], 0.f);
            #pragma unroll
            for (int kk = 0; kk < 8; kk++) {
                wmma::fragment<wmma::matrix_a, 16, 16, 8, wmma::precision::tf32, wmma::row_major> af;
                wmma::load_matrix_sync(af, &Qs[(w * 16) * AS + kk * 8], AS);
                #pragma unroll
                for (int e = 0; e < af.num_elements; e++) af.x[e] = wmma::__float_to_tf32(af.x[e]);
                #pragma unroll
                for (int n = 0; n < 4; n++) {
                    wmma::fragment<wmma::matrix_b, 16, 16, 8, wmma::precision::tf32, wmma::col_major> bf;
                    wmma::load_matrix_sync(bf, &Ks[(n * 16) * AS + kk * 8], AS);
                    #pragma unroll
                    for (int e = 0; e < bf.num_elements; e++) bf.x[e] = wmma::__float_to_tf32(bf.x[e]);
                    wmma::mma_sync(cS[n], af, bf, cS[n]);
                }
            }
            #pragma unroll
            for (int n = 0; n < 4; n++)
                wmma::store_matrix_sync(&Ss[(w * 16) * AS + n * 16], cS[n], AS, wmma::mem_row_major);
        }
        __syncthreads();   // (B)

        // online softmax: 2 threads per row, 32 cols each
        float alpha;
        {
            float4 vals[8];
            float vmax = -1e30f;
            #pragma unroll
            for (int i = 0; i < 8; i++) {
                vals[i] = *(float4*)&Ss[srow * AS + scol + i * 4];
                vmax = fmaxf(vmax, fmaxf(fmaxf(vals[i].x, vals[i].y), fmaxf(vals[i].z, vals[i].w)));
            }
            vmax = fmaxf(vmax, __shfl_xor_sync(0xffffffffu, vmax, 1));
            const float m_new = fmaxf(m_i, vmax);
            alpha = __expf(m_i - m_new);
            float s = 0.f;
            #pragma unroll
            for (int i = 0; i < 8; i++) {
                vals[i].x = __expf(vals[i].x - m_new);
                vals[i].y = __expf(vals[i].y - m_new);
                vals[i].z = __expf(vals[i].z - m_new);
                vals[i].w = __expf(vals[i].w - m_new);
                s += vals[i].x + vals[i].y + vals[i].z + vals[i].w;
                *(float4*)&Ss[srow * AS + scol + i * 4] = vals[i];
            }
            s += __shfl_xor_sync(0xffffffffu, s, 1);
            l_i = l_i * alpha + s;
            m_i = m_new;
        }
        __syncthreads();   // (C)

        // PV = P @ V  (B = V^T, col-major via Vts[d][key]), overwrite Ss strip
        {
            wmma::fragment<wmma::accumulator, 16, 16, 8, float> cO[4];
            #pragma unroll
            for (int n = 0; n < 4; n++) wmma::fill_fragment(cO[n], 0.f);
            #pragma unroll
            for (int kk = 0; kk < 8; kk++) {
                wmma::fragment<wmma::matrix_a, 16, 16, 8, wmma::precision::tf32, wmma::row_major> af;
                wmma::load_matrix_sync(af, &Ss[(w * 16) * AS + kk * 8], AS);
                #pragma unroll
                for (int e = 0; e < af.num_elements; e++) af.x[e] = wmma::__float_to_tf32(af.x[e]);
                #pragma unroll
                for (int n = 0; n < 4; n++) {
                    wmma::fragment<wmma::matrix_b, 16, 16, 8, wmma::precision::tf32, wmma::col_major> bf;
                    wmma::load_matrix_sync(bf, &Vts[(n * 16) * AS + kk * 8], AS);
                    #pragma unroll
                    for (int e = 0; e < bf.num_elements; e++) bf.x[e] = wmma::__float_to_tf32(bf.x[e]);
                    wmma::mma_sync(cO[n], af, bf, cO[n]);
                }
            }
            #pragma unroll
            for (int n = 0; n < 4; n++)
                wmma::store_matrix_sync(&Ss[(w * 16) * AS + n * 16], cO[n], AS, wmma::mem_row_major);
        }
        __syncthreads();   // (D)

        // O = O*alpha + PV
        #pragma unroll
        for (int i = 0; i < 8; i++) {
            const int idx = srow * AS + scol + i * 4;
            float4 o = *(float4*)&Os[idx];
            float4 p = *(float4*)&Ss[idx];
            o.x = o.x * alpha + p.x;
            o.y = o.y * alpha + p.y;
            o.z = o.z * alpha + p.z;
            o.w = o.w * alpha + p.w;
            *(float4*)&Os[idx] = o;
        }
        // next-iter K/V STS is ordered behind (A); Ss reuse behind next (B)
    }

    // epilogue: normalize, write [B,T,H*hd]
    const float inv = 1.f / l_i;
    #pragma unroll
    for (int i = 0; i < 8; i++) {
        const int c = scol + i * 4;
        float4 o = *(float4*)&Os[srow * AS + c];
        o.x *= inv; o.y *= inv; o.z *= inv; o.w *= inv;
        *(float4*)&Ob[(base_q + srow) * D_MODEL + hcol + c] = o;
    }
}

// ---------------------------------------------------------------------------
__global__ void add_bias_kernel(float* __restrict__ C, const float* __restrict__ bias)
{
    const int i = blockIdx.x * blockDim.x + threadIdx.x;  // float4 index
    float4 v = ((float4*)C)[i];
    float4 bb = ((const float4*)bias)[i & (D_MODEL / 4 - 1)];
    v.x += bb.x; v.y += bb.y; v.z += bb.z; v.w += bb.w;
    ((float4*)C)[i] = v;
}

// ---------------------------------------------------------------------------
extern "C" void kernel_launch(void* const* d_in, const int* in_sizes, int n_in,
                              void* d_out, int out_size)
{
    const float* query = (const float*)d_in[0];
    const float* key   = (const float*)d_in[1];
    const float* value = (const float*)d_in[2];
    const float* Wq    = (const float*)d_in[3];
    const float* bq    = (const float*)d_in[4];
    const float* Wk    = (const float*)d_in[5];
    const float* bk    = (const float*)d_in[6];
    const float* Wv    = (const float*)d_in[7];
    const float* bv    = (const float*)d_in[8];
    const float* Wo    = (const float*)d_in[9];
    const float* bo    = (const float*)d_in[10];
    float* out = (float*)d_out;

    float *pQ, *pK, *pV, *pA;
    cudaGetSymbolAddress((void**)&pQ, g_Q);
    cudaGetSymbolAddress((void**)&pK, g_K);
    cudaGetSymbolAddress((void**)&pV, g_V);
    cudaGetSymbolAddress((void**)&pA, g_Attn);

    cudaFuncSetAttribute(attn_tf32,
                         cudaFuncAttributeMaxDynamicSharedMemorySize, ATTN_SMEM);

    dim3 gemm_grid(D_MODEL / 128, MTOT / 128);   // (8, 32)

    gemm_tf32<<<gemm_grid, 256>>>(query, Wq, pQ);
    gemm_tf32<<<gemm_grid, 256>>>(key,   Wk, pK);
    gemm_tf32<<<gemm_grid, 256>>>(value, Wv, pV);

    dim3 attn_grid(SEQ / QT, NHEAD, BATCH);      // (16, 16, 2)
    attn_tf32<<<attn_grid, 256, ATTN_SMEM>>>(pQ, pK, pV, pA, bq, bk, bv);

    gemm_tf32<<<gemm_grid, 256>>>(pA, Wo, out);
    add_bias_kernel<<<(MTOT * D_MODEL / 4) / 256, 256>>>(out, bo);
}

// round 4
// speedup vs baseline: 1.8739x; 1.7148x over previous
#include <cuda_runtime.h>
#include <cstdint>
#include <mma.h>
#include <math.h>

using namespace nvcuda;

#define D_MODEL 1024
#define NHEAD 16
#define HEAD_DIM 64
#define BATCH 2
#define SEQ 2048
#define MTOT (BATCH*SEQ)   // 4096

// Scratch (allocation-free rule: __device__ globals)
__device__ float g_Q[MTOT * D_MODEL];
__device__ float g_K[MTOT * D_MODEL];
__device__ float g_V[MTOT * D_MODEL];
__device__ float g_Attn[MTOT * D_MODEL];

// ---------------------------------------------------------------------------
// helpers
// ---------------------------------------------------------------------------
__device__ __forceinline__ unsigned f2tf(float x) {
    unsigned u;
    asm("cvt.rna.tf32.f32 %0, %1;" : "=r"(u) : "f"(x));
    return u;
}

__device__ __forceinline__ void mma8(float* c, const unsigned* a,
                                     unsigned b0, unsigned b1) {
    asm volatile(
        "mma.sync.aligned.m16n8k8.row.col.f32.tf32.tf32.f32 "
        "{%0,%1,%2,%3}, {%4,%5,%6,%7}, {%8,%9}, {%0,%1,%2,%3};"
        : "+f"(c[0]), "+f"(c[1]), "+f"(c[2]), "+f"(c[3])
        : "r"(a[0]), "r"(a[1]), "r"(a[2]), "r"(a[3]), "r"(b0), "r"(b1));
}

__device__ __forceinline__ void cp_async16(void* dst, const void* src) {
    unsigned int d = (unsigned int)__cvta_generic_to_shared(dst);
    asm volatile("cp.async.cg.shared.global [%0], [%1], 16;" :: "r"(d), "l"(src));
}
#define CP_COMMIT() asm volatile("cp.async.commit_group;")
#define CP_WAIT1()  asm volatile("cp.async.wait_group 1;")

// ---------------------------------------------------------------------------
// tf32 GEMM: C[M,N] = A[M,K] @ W[N,K]^T   (no bias; M=4096, N=K=1024)
// 128x128 block, BK=32, 8 warps (2x4), warp tile 64x32, wmma m16n16k8 tf32.
// ---------------------------------------------------------------------------
#define GS 40

__global__ __launch_bounds__(256) void gemm_tf32(
    const float* __restrict__ A, const float* __restrict__ W,
    float* __restrict__ C)
{
    __shared__ float As[128 * GS];
    __shared__ float Ws[128 * GS];

    const int m0 = blockIdx.y * 128;
    const int n0 = blockIdx.x * 128;
    const int t  = threadIdx.x;
    const int wid = t >> 5;
    const int wm = wid >> 2;
    const int wn = wid & 3;
    const int lrow = t >> 1;
    const int lcol = (t & 1) * 16;

    wmma::fragment<wmma::accumulator, 16, 16, 8, float> acc[4][2];
    #pragma unroll
    for (int i = 0; i < 4; i++)
        #pragma unroll
        for (int j = 0; j < 2; j++) wmma::fill_fragment(acc[i][j], 0.f);

    const float* Ap = A + (m0 + lrow) * D_MODEL + lcol;
    const float* Wp = W + (n0 + lrow) * D_MODEL + lcol;

    float4 ra[4], rw[4];
    #pragma unroll
    for (int i = 0; i < 4; i++) {
        ra[i] = *(const float4*)(Ap + i * 4);
        rw[i] = *(const float4*)(Wp + i * 4);
    }

    for (int k0 = 0; k0 < D_MODEL; k0 += 32) {
        #pragma unroll
        for (int i = 0; i < 4; i++) {
            *(float4*)&As[lrow * GS + lcol + i * 4] = ra[i];
            *(float4*)&Ws[lrow * GS + lcol + i * 4] = rw[i];
        }
        __syncthreads();

        if (k0 + 32 < D_MODEL) {
            #pragma unroll
            for (int i = 0; i < 4; i++) {
                ra[i] = *(const float4*)(Ap + k0 + 32 + i * 4);
                rw[i] = *(const float4*)(Wp + k0 + 32 + i * 4);
            }
        }

        #pragma unroll
        for (int kk = 0; kk < 4; kk++) {
            wmma::fragment<wmma::matrix_a, 16, 16, 8, wmma::precision::tf32, wmma::row_major> af[4];
            wmma::fragment<wmma::matrix_b, 16, 16, 8, wmma::precision::tf32, wmma::col_major> bf[2];
            #pragma unroll
            for (int i = 0; i < 4; i++) {
                wmma::load_matrix_sync(af[i], &As[(wm * 64 + i * 16) * GS + kk * 8], GS);
                #pragma unroll
                for (int e = 0; e < af[i].num_elements; e++)
                    af[i].x[e] = wmma::__float_to_tf32(af[i].x[e]);
            }
            #pragma unroll
            for (int j = 0; j < 2; j++) {
                wmma::load_matrix_sync(bf[j], &Ws[(wn * 32 + j * 16) * GS + kk * 8], GS);
                #pragma unroll
                for (int e = 0; e < bf[j].num_elements; e++)
                    bf[j].x[e] = wmma::__float_to_tf32(bf[j].x[e]);
            }
            #pragma unroll
            for (int i = 0; i < 4; i++)
                #pragma unroll
                for (int j = 0; j < 2; j++)
                    wmma::mma_sync(acc[i][j], af[i], bf[j], acc[i][j]);
        }
        __syncthreads();
    }

    #pragma unroll
    for (int i = 0; i < 4; i++)
        #pragma unroll
        for (int j = 0; j < 2; j++)
            wmma::store_matrix_sync(
                &C[(m0 + wm * 64 + i * 16) * D_MODEL + n0 + wn * 32 + j * 16],
                acc[i][j], D_MODEL, wmma::mem_row_major);
}

// ---------------------------------------------------------------------------
// C = (C + bias) * scale  (elementwise, bias broadcast over rows)
// ---------------------------------------------------------------------------
__global__ void bias_scale_kernel(float* __restrict__ C,
                                  const float* __restrict__ bias, float scale)
{
    const int i = blockIdx.x * blockDim.x + threadIdx.x;
    float4 v = ((float4*)C)[i];
    float4 bb = ((const float4*)bias)[i & (D_MODEL / 4 - 1)];
    v.x = (v.x + bb.x) * scale;
    v.y = (v.y + bb.y) * scale;
    v.z = (v.z + bb.z) * scale;
    v.w = (v.w + bb.w) * scale;
    ((float4*)C)[i] = v;
}

// ---------------------------------------------------------------------------
// Flash attention, mma.sync m16n8k8 tf32, register accumulators.
// Block = (q-tile 128, head, batch), 8 warps; warp w owns query rows
// [w*16, w*16+16). Per-thread fragment rows: r0 = w*16 + lane/4, r1 = r0+8.
// smem: P/Q strip [128][68] (warp-private), K double-buf [2][64][68],
//       V double-buf [2][64][72].
// ---------------------------------------------------------------------------
#define KS 68
#define VS 72
#define PS 68
#define NTILES (SEQ / 64)
#define ATTN_SMEM ((128*PS + 2*64*KS + 2*64*VS) * (int)sizeof(float))  // 106496

__global__ __launch_bounds__(256, 2) void attn_mma(
    const float* __restrict__ Qb, const float* __restrict__ Kb,
    const float* __restrict__ Vb, float* __restrict__ Ob)
{
    extern __shared__ float sm[];
    float* Ps = sm;                         // [128][PS]  (Q staging, then P)
    float* Kbuf = Ps + 128 * PS;            // [2][64][KS]
    float* Vbuf = Kbuf + 2 * 64 * KS;       // [2][64][VS]

    const int qt = blockIdx.x, h = blockIdx.y, b = blockIdx.z;
    const int t = threadIdx.x, w = t >> 5, lane = t & 31;
    const int g4 = lane >> 2, q4 = lane & 3;
    const int base_q = b * SEQ + qt * 128;
    const int hcol = h * HEAD_DIM;

    // --- stage tile 0 of K/V via cp.async (overlaps Q setup) ---
    {
        const int base_k = b * SEQ;
        #pragma unroll
        for (int i = 0; i < 4; i++) {
            const int id = t + i * 256;
            const int row = id >> 4, seg = id & 15;
            const size_t g = (size_t)(base_k + row) * D_MODEL + hcol + seg * 4;
            cp_async16(&Kbuf[row * KS + seg * 4], Kb + g);
            cp_async16(&Vbuf[row * VS + seg * 4], Vb + g);
        }
    }
    CP_COMMIT();

    // --- stage Q (warp-local rows) and load A-fragments (pre-converted tf32) ---
    {
        const int r = t >> 1;
        const int c0 = (t & 1) * 32;
        #pragma unroll
        for (int i = 0; i < 8; i++)
            *(float4*)&Ps[r * PS + c0 + i * 4] =
                *(const float4*)&Qb[(base_q + r) * D_MODEL + hcol + c0 + i * 4];
    }
    __syncwarp();

    unsigned qa[8][4];
    #pragma unroll
    for (int kk = 0; kk < 8; kk++) {
        qa[kk][0] = f2tf(Ps[(w * 16 + g4)     * PS + kk * 8 + q4]);
        qa[kk][1] = f2tf(Ps[(w * 16 + g4 + 8) * PS + kk * 8 + q4]);
        qa[kk][2] = f2tf(Ps[(w * 16 + g4)     * PS + kk * 8 + q4 + 4]);
        qa[kk][3] = f2tf(Ps[(w * 16 + g4 + 8) * PS + kk * 8 + q4 + 4]);
    }
    __syncwarp();   // Ps free for P reuse

    float of[8][4];
    #pragma unroll
    for (int n = 0; n < 8; n++)
        of[n][0] = of[n][1] = of[n][2] = of[n][3] = 0.f;
    float m0r = -1e30f, m1r = -1e30f, l0r = 0.f, l1r = 0.f;

    for (int jt = 0; jt < NTILES; jt++) {
        float* Kc = Kbuf + (jt & 1) * 64 * KS;
        float* Vc = Vbuf + (jt & 1) * 64 * VS;

        if (jt + 1 < NTILES) {
            float* Kn = Kbuf + ((jt + 1) & 1) * 64 * KS;
            float* Vn = Vbuf + ((jt + 1) & 1) * 64 * VS;
            const int base_k = b * SEQ + (jt + 1) * 64;
            #pragma unroll
            for (int i = 0; i < 4; i++) {
                const int id = t + i * 256;
                const int row = id >> 4, seg = id & 15;
                const size_t g = (size_t)(base_k + row) * D_MODEL + hcol + seg * 4;
                cp_async16(&Kn[row * KS + seg * 4], Kb + g);
                cp_async16(&Vn[row * VS + seg * 4], Vb + g);
            }
        }
        CP_COMMIT();
        CP_WAIT1();          // tile jt resident; jt+1 in flight
        __syncthreads();

        // ---- S = Q @ K^T : 8 n-blocks of 8 keys ----
        float sfr[8][4];
        #pragma unroll
        for (int n = 0; n < 8; n++)
            sfr[n][0] = sfr[n][1] = sfr[n][2] = sfr[n][3] = 0.f;
        #pragma unroll
        for (int kk = 0; kk < 8; kk++) {
            #pragma unroll
            for (int n = 0; n < 8; n++) {
                const float* kp = &Kc[(n * 8 + g4) * KS + kk * 8 + q4];
                unsigned b0 = f2tf(kp[0]);
                unsigned b1 = f2tf(kp[4]);
                mma8(sfr[n], qa[kk], b0, b1);
            }
        }

        // ---- online softmax in registers ----
        float mx0 = -1e30f, mx1 = -1e30f;
        #pragma unroll
        for (int n = 0; n < 8; n++) {
            mx0 = fmaxf(mx0, fmaxf(sfr[n][0], sfr[n][1]));
            mx1 = fmaxf(mx1, fmaxf(sfr[n][2], sfr[n][3]));
        }
        mx0 = fmaxf(mx0, __shfl_xor_sync(0xffffffffu, mx0, 1));
        mx0 = fmaxf(mx0, __shfl_xor_sync(0xffffffffu, mx0, 2));
        mx1 = fmaxf(mx1, __shfl_xor_sync(0xffffffffu, mx1, 1));
        mx1 = fmaxf(mx1, __shfl_xor_sync(0xffffffffu, mx1, 2));

        const float mn0 = fmaxf(m0r, mx0);
        const float mn1 = fmaxf(m1r, mx1);
        const float a0 = __expf(m0r - mn0);
        const float a1 = __expf(m1r - mn1);
        m0r = mn0; m1r = mn1;

        float s0 = 0.f, s1 = 0.f;
        #pragma unroll
        for (int n = 0; n < 8; n++) {
            sfr[n][0] = __expf(sfr[n][0] - mn0);
            sfr[n][1] = __expf(sfr[n][1] - mn0);
            sfr[n][2] = __expf(sfr[n][2] - mn1);
            sfr[n][3] = __expf(sfr[n][3] - mn1);
            s0 += sfr[n][0] + sfr[n][1];
            s1 += sfr[n][2] + sfr[n][3];
            // O rescale fused here
            of[n][0] *= a0; of[n][1] *= a0;
            of[n][2] *= a1; of[n][3] *= a1;
            // stash P (warp-private strip)
            *(float2*)&Ps[(w * 16 + g4)     * PS + n * 8 + 2 * q4] =
                make_float2(sfr[n][0], sfr[n][1]);
            *(float2*)&Ps[(w * 16 + g4 + 8) * PS + n * 8 + 2 * q4] =
                make_float2(sfr[n][2], sfr[n][3]);
        }
        s0 += __shfl_xor_sync(0xffffffffu, s0, 1);
        s0 += __shfl_xor_sync(0xffffffffu, s0, 2);
        s1 += __shfl_xor_sync(0xffffffffu, s1, 1);
        s1 += __shfl_xor_sync(0xffffffffu, s1, 2);
        l0r = l0r * a0 + s0;
        l1r = l1r * a1 + s1;
        __syncwarp();

        // ---- O += P @ V ----
        #pragma unroll
        for (int kk = 0; kk < 8; kk++) {
            unsigned pa[4];
            pa[0] = f2tf(Ps[(w * 16 + g4)     * PS + kk * 8 + q4]);
            pa[1] = f2tf(Ps[(w * 16 + g4 + 8) * PS + kk * 8 + q4]);
            pa[2] = f2tf(Ps[(w * 16 + g4)     * PS + kk * 8 + q4 + 4]);
            pa[3] = f2tf(Ps[(w * 16 + g4 + 8) * PS + kk * 8 + q4 + 4]);
            #pragma unroll
            for (int n = 0; n < 8; n++) {
                unsigned b0 = f2tf(Vc[(kk * 8 + q4)     * VS + n * 8 + g4]);
                unsigned b1 = f2tf(Vc[(kk * 8 + q4 + 4) * VS + n * 8 + g4]);
                mma8(of[n], pa, b0, b1);
            }
        }
        __syncwarp();
        __syncthreads();   // all warps done with Kc/Vc before restaging
    }

    // ---- epilogue: normalize, write [B,T,H*hd] ----
    const float inv0 = 1.f / l0r;
    const float inv1 = 1.f / l1r;
    const int r0 = base_q + w * 16 + g4;
    #pragma unroll
    for (int n = 0; n < 8; n++) {
        const int c = hcol + n * 8 + 2 * q4;
        *(float2*)&Ob[r0 * D_MODEL + c] =
            make_float2(of[n][0] * inv0, of[n][1] * inv0);
        *(float2*)&Ob[(r0 + 8) * D_MODEL + c] =
            make_float2(of[n][2] * inv1, of[n][3] * inv1);
    }
}

// ---------------------------------------------------------------------------
extern "C" void kernel_launch(void* const* d_in, const int* in_sizes, int n_in,
                              void* d_out, int out_size)
{
    const float* query = (const float*)d_in[0];
    const float* key   = (const float*)d_in[1];
    const float* value = (const float*)d_in[2];
    const float* Wq    = (const float*)d_in[3];
    const float* bq    = (const float*)d_in[4];
    const float* Wk    = (const float*)d_in[5];
    const float* bk    = (const float*)d_in[6];
    const float* Wv    = (const float*)d_in[7];
    const float* bv    = (const float*)d_in[8];
    const float* Wo    = (const float*)d_in[9];
    const float* bo    = (const float*)d_in[10];
    float* out = (float*)d_out;

    float *pQ, *pK, *pV, *pA;
    cudaGetSymbolAddress((void**)&pQ, g_Q);
    cudaGetSymbolAddress((void**)&pK, g_K);
    cudaGetSymbolAddress((void**)&pV, g_V);
    cudaGetSymbolAddress((void**)&pA, g_Attn);

    cudaFuncSetAttribute(attn_mma,
                         cudaFuncAttributeMaxDynamicSharedMemorySize, ATTN_SMEM);

    dim3 gemm_grid(D_MODEL / 128, MTOT / 128);   // (8, 32)
    const int eb = (MTOT * D_MODEL / 4) / 256;
    const float qscale = 0.125f;                 // 1/sqrt(64)

    gemm_tf32<<<gemm_grid, 256>>>(query, Wq, pQ);
    bias_scale_kernel<<<eb, 256>>>(pQ, bq, qscale);
    gemm_tf32<<<gemm_grid, 256>>>(key,   Wk, pK);
    bias_scale_kernel<<<eb, 256>>>(pK, bk, 1.f);
    gemm_tf32<<<gemm_grid, 256>>>(value, Wv, pV);
    bias_scale_kernel<<<eb, 256>>>(pV, bv, 1.f);

    dim3 attn_grid(SEQ / 128, NHEAD, BATCH);     // (16, 16, 2)
    attn_mma<<<attn_grid, 256, ATTN_SMEM>>>(pQ, pK, pV, pA);

    gemm_tf32<<<gemm_grid, 256>>>(pA, Wo, out);
    bias_scale_kernel<<<eb, 256>>>(out, bo, 1.f);
}

// round 5
// speedup vs baseline: 2.2090x; 1.1788x over previous
#include <cuda_runtime.h>
#include <cstdint>
#include <mma.h>
#include <math.h>

using namespace nvcuda;

#define D_MODEL 1024
#define NHEAD 16
#define HEAD_DIM 64
#define BATCH 2
#define SEQ 2048
#define MTOT (BATCH*SEQ)   // 4096

// Scratch (allocation-free rule: __device__ globals)
__device__ float g_Q[MTOT * D_MODEL];
__device__ float g_K[MTOT * D_MODEL];
__device__ float g_V[MTOT * D_MODEL];
__device__ float g_Attn[MTOT * D_MODEL];

// ---------------------------------------------------------------------------
// helpers
// ---------------------------------------------------------------------------
__device__ __forceinline__ unsigned f2tf(float x) {
    unsigned u;
    asm("cvt.rna.tf32.f32 %0, %1;" : "=r"(u) : "f"(x));
    return u;
}

__device__ __forceinline__ void mma8(float* c, const unsigned* a,
                                     unsigned b0, unsigned b1) {
    asm volatile(
        "mma.sync.aligned.m16n8k8.row.col.f32.tf32.tf32.f32 "
        "{%0,%1,%2,%3}, {%4,%5,%6,%7}, {%8,%9}, {%0,%1,%2,%3};"
        : "+f"(c[0]), "+f"(c[1]), "+f"(c[2]), "+f"(c[3])
        : "r"(a[0]), "r"(a[1]), "r"(a[2]), "r"(a[3]), "r"(b0), "r"(b1));
}

__device__ __forceinline__ void cp_async16(void* dst, const void* src) {
    unsigned int d = (unsigned int)__cvta_generic_to_shared(dst);
    asm volatile("cp.async.cg.shared.global [%0], [%1], 16;" :: "r"(d), "l"(src));
}
#define CP_COMMIT() asm volatile("cp.async.commit_group;")
#define CP_WAIT1()  asm volatile("cp.async.wait_group 1;")

// ---------------------------------------------------------------------------
// tf32 GEMM, cp.async double-buffered, fused epilogue:
//   C = (A @ W^T + bias) * scale        (ROUND: stored values tf32-rounded)
// 128x128 block, BK=32, 8 warps (2x4), warp tile 64x32, wmma m16n16k8 tf32.
// ---------------------------------------------------------------------------
#define GS 40
#define CS 132
#define GEMM_SMEM (4 * 128 * GS * (int)sizeof(float))   // 81920 bytes

template<bool ROUND>
__global__ __launch_bounds__(256, 2) void gemm_tf32(
    const float* __restrict__ A, const float* __restrict__ W,
    const float* __restrict__ bias, float scale, float* __restrict__ C)
{
    extern __shared__ float sm[];
    float* As = sm;                  // [2][128*GS]
    float* Ws = sm + 2 * 128 * GS;   // [2][128*GS]

    const int m0 = blockIdx.y * 128;
    const int n0 = blockIdx.x * 128;
    const int t  = threadIdx.x;
    const int wid = t >> 5;
    const int wm = wid >> 2;
    const int wn = wid & 3;
    const int lrow = t >> 1;
    const int lseg = (t & 1) * 16;

    wmma::fragment<wmma::accumulator, 16, 16, 8, float> acc[4][2];
    #pragma unroll
    for (int i = 0; i < 4; i++)
        #pragma unroll
        for (int j = 0; j < 2; j++) wmma::fill_fragment(acc[i][j], 0.f);

    const float* Ap = A + (size_t)(m0 + lrow) * D_MODEL + lseg;
    const float* Wp = W + (size_t)(n0 + lrow) * D_MODEL + lseg;

    // stage k-tile 0 into buf 0
    #pragma unroll
    for (int i = 0; i < 4; i++) {
        cp_async16(&As[lrow * GS + lseg + i * 4], Ap + i * 4);
        cp_async16(&Ws[lrow * GS + lseg + i * 4], Wp + i * 4);
    }
    CP_COMMIT();

    const int NKT = D_MODEL / 32;
    for (int kt = 0; kt < NKT; kt++) {
        if (kt + 1 < NKT) {
            float* An = As + ((kt + 1) & 1) * 128 * GS;
            float* Wn = Ws + ((kt + 1) & 1) * 128 * GS;
            const int k0 = (kt + 1) * 32;
            #pragma unroll
            for (int i = 0; i < 4; i++) {
                cp_async16(&An[lrow * GS + lseg + i * 4], Ap + k0 + i * 4);
                cp_async16(&Wn[lrow * GS + lseg + i * 4], Wp + k0 + i * 4);
            }
        }
        CP_COMMIT();
        CP_WAIT1();
        __syncthreads();

        float* Ac = As + (kt & 1) * 128 * GS;
        float* Wc = Ws + (kt & 1) * 128 * GS;

        #pragma unroll
        for (int kk = 0; kk < 4; kk++) {
            wmma::fragment<wmma::matrix_a, 16, 16, 8, wmma::precision::tf32, wmma::row_major> af[4];
            wmma::fragment<wmma::matrix_b, 16, 16, 8, wmma::precision::tf32, wmma::col_major> bf[2];
            #pragma unroll
            for (int i = 0; i < 4; i++) {
                wmma::load_matrix_sync(af[i], &Ac[(wm * 64 + i * 16) * GS + kk * 8], GS);
                #pragma unroll
                for (int e = 0; e < af[i].num_elements; e++)
                    af[i].x[e] = wmma::__float_to_tf32(af[i].x[e]);
            }
            #pragma unroll
            for (int j = 0; j < 2; j++) {
                wmma::load_matrix_sync(bf[j], &Wc[(wn * 32 + j * 16) * GS + kk * 8], GS);
                #pragma unroll
                for (int e = 0; e < bf[j].num_elements; e++)
                    bf[j].x[e] = wmma::__float_to_tf32(bf[j].x[e]);
            }
            #pragma unroll
            for (int i = 0; i < 4; i++)
                #pragma unroll
                for (int j = 0; j < 2; j++)
                    wmma::mma_sync(acc[i][j], af[i], bf[j], acc[i][j]);
        }
        __syncthreads();
    }

    // ---- fused epilogue: frags -> smem -> (+bias)*scale [-> tf32 round] -> C
    float* Cs = sm;   // 128 x CS = 67584 floats... (16896 floats, fits in 81920B*? yes: 128*132*4 = 67584 bytes < 81920)
    #pragma unroll
    for (int i = 0; i < 4; i++)
        #pragma unroll
        for (int j = 0; j < 2; j++)
            wmma::store_matrix_sync(&Cs[(wm * 64 + i * 16) * CS + wn * 32 + j * 16],
                                    acc[i][j], CS, wmma::mem_row_major);
    __syncthreads();

    {
        const int r = t >> 1;
        const int c0 = (t & 1) * 64;
        float* dst = C + (size_t)(m0 + r) * D_MODEL + n0 + c0;
        const float* brow = bias + n0 + c0;
        #pragma unroll
        for (int i = 0; i < 16; i++) {
            float4 v = *(float4*)&Cs[r * CS + c0 + i * 4];
            float4 bb = *(const float4*)(brow + i * 4);
            v.x = (v.x + bb.x) * scale;
            v.y = (v.y + bb.y) * scale;
            v.z = (v.z + bb.z) * scale;
            v.w = (v.w + bb.w) * scale;
            if (ROUND) {
                v.x = __uint_as_float(f2tf(v.x));
                v.y = __uint_as_float(f2tf(v.y));
                v.z = __uint_as_float(f2tf(v.z));
                v.w = __uint_as_float(f2tf(v.w));
            }
            *(float4*)(dst + i * 4) = v;
        }
    }
}

// ---------------------------------------------------------------------------
// Flash attention, mma.sync m16n8k8 tf32, register accumulators.
// Q/K/V arrive tf32-pre-rounded, so fragment loads are bit reinterprets.
// ---------------------------------------------------------------------------
#define KS 68
#define VS 72
#define PS 68
#define NTILES (SEQ / 64)
#define ATTN_SMEM ((128*PS + 2*64*KS + 2*64*VS) * (int)sizeof(float))  // 106496

__global__ __launch_bounds__(256, 2) void attn_mma(
    const float* __restrict__ Qb, const float* __restrict__ Kb,
    const float* __restrict__ Vb, float* __restrict__ Ob)
{
    extern __shared__ float sm[];
    float* Ps = sm;                         // [128][PS]  (Q staging, then P)
    float* Kbuf = Ps + 128 * PS;            // [2][64][KS]
    float* Vbuf = Kbuf + 2 * 64 * KS;       // [2][64][VS]

    const int qt = blockIdx.x, h = blockIdx.y, b = blockIdx.z;
    const int t = threadIdx.x, w = t >> 5, lane = t & 31;
    const int g4 = lane >> 2, q4 = lane & 3;
    const int base_q = b * SEQ + qt * 128;
    const int hcol = h * HEAD_DIM;

    // --- stage tile 0 of K/V via cp.async ---
    {
        const int base_k = b * SEQ;
        #pragma unroll
        for (int i = 0; i < 4; i++) {
            const int id = t + i * 256;
            const int row = id >> 4, seg = id & 15;
            const size_t g = (size_t)(base_k + row) * D_MODEL + hcol + seg * 4;
            cp_async16(&Kbuf[row * KS + seg * 4], Kb + g);
            cp_async16(&Vbuf[row * VS + seg * 4], Vb + g);
        }
    }
    CP_COMMIT();

    // --- stage Q and load A-fragments (already tf32 bit patterns) ---
    {
        const int r = t >> 1;
        const int c0 = (t & 1) * 32;
        #pragma unroll
        for (int i = 0; i < 8; i++)
            *(float4*)&Ps[r * PS + c0 + i * 4] =
                *(const float4*)&Qb[(size_t)(base_q + r) * D_MODEL + hcol + c0 + i * 4];
    }
    __syncwarp();

    unsigned qa[8][4];
    #pragma unroll
    for (int kk = 0; kk < 8; kk++) {
        qa[kk][0] = __float_as_uint(Ps[(w * 16 + g4)     * PS + kk * 8 + q4]);
        qa[kk][1] = __float_as_uint(Ps[(w * 16 + g4 + 8) * PS + kk * 8 + q4]);
        qa[kk][2] = __float_as_uint(Ps[(w * 16 + g4)     * PS + kk * 8 + q4 + 4]);
        qa[kk][3] = __float_as_uint(Ps[(w * 16 + g4 + 8) * PS + kk * 8 + q4 + 4]);
    }
    __syncwarp();   // Ps free for P reuse

    float of[8][4];
    #pragma unroll
    for (int n = 0; n < 8; n++)
        of[n][0] = of[n][1] = of[n][2] = of[n][3] = 0.f;
    float m0r = -1e30f, m1r = -1e30f, l0r = 0.f, l1r = 0.f;

    for (int jt = 0; jt < NTILES; jt++) {
        float* Kc = Kbuf + (jt & 1) * 64 * KS;
        float* Vc = Vbuf + (jt & 1) * 64 * VS;

        if (jt + 1 < NTILES) {
            float* Kn = Kbuf + ((jt + 1) & 1) * 64 * KS;
            float* Vn = Vbuf + ((jt + 1) & 1) * 64 * VS;
            const int base_k = b * SEQ + (jt + 1) * 64;
            #pragma unroll
            for (int i = 0; i < 4; i++) {
                const int id = t + i * 256;
                const int row = id >> 4, seg = id & 15;
                const size_t g = (size_t)(base_k + row) * D_MODEL + hcol + seg * 4;
                cp_async16(&Kn[row * KS + seg * 4], Kb + g);
                cp_async16(&Vn[row * VS + seg * 4], Vb + g);
            }
        }
        CP_COMMIT();
        CP_WAIT1();          // tile jt resident; jt+1 in flight
        __syncthreads();

        // ---- S = Q @ K^T ----
        float sfr[8][4];
        #pragma unroll
        for (int n = 0; n < 8; n++)
            sfr[n][0] = sfr[n][1] = sfr[n][2] = sfr[n][3] = 0.f;
        #pragma unroll
        for (int kk = 0; kk < 8; kk++) {
            #pragma unroll
            for (int n = 0; n < 8; n++) {
                const float* kp = &Kc[(n * 8 + g4) * KS + kk * 8 + q4];
                unsigned b0 = __float_as_uint(kp[0]);
                unsigned b1 = __float_as_uint(kp[4]);
                mma8(sfr[n], qa[kk], b0, b1);
            }
        }

        // ---- online softmax in registers ----
        float mx0 = -1e30f, mx1 = -1e30f;
        #pragma unroll
        for (int n = 0; n < 8; n++) {
            mx0 = fmaxf(mx0, fmaxf(sfr[n][0], sfr[n][1]));
            mx1 = fmaxf(mx1, fmaxf(sfr[n][2], sfr[n][3]));
        }
        mx0 = fmaxf(mx0, __shfl_xor_sync(0xffffffffu, mx0, 1));
        mx0 = fmaxf(mx0, __shfl_xor_sync(0xffffffffu, mx0, 2));
        mx1 = fmaxf(mx1, __shfl_xor_sync(0xffffffffu, mx1, 1));
        mx1 = fmaxf(mx1, __shfl_xor_sync(0xffffffffu, mx1, 2));

        const float mn0 = fmaxf(m0r, mx0);
        const float mn1 = fmaxf(m1r, mx1);
        const float a0 = __expf(m0r - mn0);
        const float a1 = __expf(m1r - mn1);
        m0r = mn0; m1r = mn1;

        float s0 = 0.f, s1 = 0.f;
        #pragma unroll
        for (int n = 0; n < 8; n++) {
            sfr[n][0] = __expf(sfr[n][0] - mn0);
            sfr[n][1] = __expf(sfr[n][1] - mn0);
            sfr[n][2] = __expf(sfr[n][2] - mn1);
            sfr[n][3] = __expf(sfr[n][3] - mn1);
            s0 += sfr[n][0] + sfr[n][1];
            s1 += sfr[n][2] + sfr[n][3];
            of[n][0] *= a0; of[n][1] *= a0;
            of[n][2] *= a1; of[n][3] *= a1;
            *(float2*)&Ps[(w * 16 + g4)     * PS + n * 8 + 2 * q4] =
                make_float2(sfr[n][0], sfr[n][1]);
            *(float2*)&Ps[(w * 16 + g4 + 8) * PS + n * 8 + 2 * q4] =
                make_float2(sfr[n][2], sfr[n][3]);
        }
        s0 += __shfl_xor_sync(0xffffffffu, s0, 1);
        s0 += __shfl_xor_sync(0xffffffffu, s0, 2);
        s1 += __shfl_xor_sync(0xffffffffu, s1, 1);
        s1 += __shfl_xor_sync(0xffffffffu, s1, 2);
        l0r = l0r * a0 + s0;
        l1r = l1r * a1 + s1;
        __syncwarp();

        // ---- O += P @ V ----
        #pragma unroll
        for (int kk = 0; kk < 8; kk++) {
            unsigned pa[4];
            pa[0] = f2tf(Ps[(w * 16 + g4)     * PS + kk * 8 + q4]);
            pa[1] = f2tf(Ps[(w * 16 + g4 + 8) * PS + kk * 8 + q4]);
            pa[2] = f2tf(Ps[(w * 16 + g4)     * PS + kk * 8 + q4 + 4]);
            pa[3] = f2tf(Ps[(w * 16 + g4 + 8) * PS + kk * 8 + q4 + 4]);
            #pragma unroll
            for (int n = 0; n < 8; n++) {
                unsigned b0 = __float_as_uint(Vc[(kk * 8 + q4)     * VS + n * 8 + g4]);
                unsigned b1 = __float_as_uint(Vc[(kk * 8 + q4 + 4) * VS + n * 8 + g4]);
                mma8(of[n], pa, b0, b1);
            }
        }
        __syncwarp();
        __syncthreads();   // all warps done with Kc/Vc before restaging
    }

    // ---- epilogue: normalize, write [B,T,H*hd] ----
    const float inv0 = 1.f / l0r;
    const float inv1 = 1.f / l1r;
    const int r0 = base_q + w * 16 + g4;
    #pragma unroll
    for (int n = 0; n < 8; n++) {
        const int c = hcol + n * 8 + 2 * q4;
        *(float2*)&Ob[(size_t)r0 * D_MODEL + c] =
            make_float2(of[n][0] * inv0, of[n][1] * inv0);
        *(float2*)&Ob[(size_t)(r0 + 8) * D_MODEL + c] =
            make_float2(of[n][2] * inv1, of[n][3] * inv1);
    }
}

// ---------------------------------------------------------------------------
extern "C" void kernel_launch(void* const* d_in, const int* in_sizes, int n_in,
                              void* d_out, int out_size)
{
    const float* query = (const float*)d_in[0];
    const float* key   = (const float*)d_in[1];
    const float* value = (const float*)d_in[2];
    const float* Wq    = (const float*)d_in[3];
    const float* bq    = (const float*)d_in[4];
    const float* Wk    = (const float*)d_in[5];
    const float* bk    = (const float*)d_in[6];
    const float* Wv    = (const float*)d_in[7];
    const float* bv    = (const float*)d_in[8];
    const float* Wo    = (const float*)d_in[9];
    const float* bo    = (const float*)d_in[10];
    float* out = (float*)d_out;

    float *pQ, *pK, *pV, *pA;
    cudaGetSymbolAddress((void**)&pQ, g_Q);
    cudaGetSymbolAddress((void**)&pK, g_K);
    cudaGetSymbolAddress((void**)&pV, g_V);
    cudaGetSymbolAddress((void**)&pA, g_Attn);

    cudaFuncSetAttribute(gemm_tf32<true>,
                         cudaFuncAttributeMaxDynamicSharedMemorySize, GEMM_SMEM);
    cudaFuncSetAttribute(gemm_tf32<false>,
                         cudaFuncAttributeMaxDynamicSharedMemorySize, GEMM_SMEM);
    cudaFuncSetAttribute(attn_mma,
                         cudaFuncAttributeMaxDynamicSharedMemorySize, ATTN_SMEM);

    dim3 gemm_grid(D_MODEL / 128, MTOT / 128);   // (8, 32)
    const float qscale = 0.125f;                 // 1/sqrt(64)

    gemm_tf32<true><<<gemm_grid, 256, GEMM_SMEM>>>(query, Wq, bq, qscale, pQ);
    gemm_tf32<true><<<gemm_grid, 256, GEMM_SMEM>>>(key,   Wk, bk, 1.f,    pK);
    gemm_tf32<true><<<gemm_grid, 256, GEMM_SMEM>>>(value, Wv, bv, 1.f,    pV);

    dim3 attn_grid(SEQ / 128, NHEAD, BATCH);     // (16, 16, 2)
    attn_mma<<<attn_grid, 256, ATTN_SMEM>>>(pQ, pK, pV, pA);

    gemm_tf32<false><<<gemm_grid, 256, GEMM_SMEM>>>(pA, Wo, bo, 1.f, out);
}

// round 6
// speedup vs baseline: 3.2197x; 1.4575x over previous
#include <cuda_runtime.h>
#include <cstdint>
#include <math.h>

#define D_MODEL 1024
#define NHEAD 16
#define HEAD_DIM 64
#define BATCH 2
#define SEQ 2048
#define MTOT (BATCH*SEQ)   // 4096

// Scratch (allocation-free rule: __device__ globals)
__device__ float g_Q[MTOT * D_MODEL];
__device__ float g_K[MTOT * D_MODEL];
__device__ float g_V[MTOT * D_MODEL];
__device__ float g_Attn[MTOT * D_MODEL];

// ---------------------------------------------------------------------------
// helpers
// ---------------------------------------------------------------------------
__device__ __forceinline__ unsigned f2tf(float x) {
    unsigned u;
    asm("cvt.rna.tf32.f32 %0, %1;" : "=r"(u) : "f"(x));
    return u;
}

__device__ __forceinline__ void mma8(float* c, const unsigned* a,
                                     unsigned b0, unsigned b1) {
    asm volatile(
        "mma.sync.aligned.m16n8k8.row.col.f32.tf32.tf32.f32 "
        "{%0,%1,%2,%3}, {%4,%5,%6,%7}, {%8,%9}, {%0,%1,%2,%3};"
        : "+f"(c[0]), "+f"(c[1]), "+f"(c[2]), "+f"(c[3])
        : "r"(a[0]), "r"(a[1]), "r"(a[2]), "r"(a[3]), "r"(b0), "r"(b1));
}

__device__ __forceinline__ void cp_async16(void* dst, const void* src) {
    unsigned int d = (unsigned int)__cvta_generic_to_shared(dst);
    asm volatile("cp.async.cg.shared.global [%0], [%1], 16;" :: "r"(d), "l"(src));
}
#define CP_COMMIT() asm volatile("cp.async.commit_group;")
#define CP_WAIT1()  asm volatile("cp.async.wait_group 1;")

__device__ __forceinline__ float4 round4(float4 v, float scale, float4 bb, bool round_out) {
    v.x = (v.x + bb.x) * scale; v.y = (v.y + bb.y) * scale;
    v.z = (v.z + bb.z) * scale; v.w = (v.w + bb.w) * scale;
    if (round_out) {
        v.x = __uint_as_float(f2tf(v.x)); v.y = __uint_as_float(f2tf(v.y));
        v.z = __uint_as_float(f2tf(v.z)); v.w = __uint_as_float(f2tf(v.w));
    }
    return v;
}

// ---------------------------------------------------------------------------
// Hand-rolled tf32 GEMM:  C = (A @ W^T + bias) * scale  [tf32-round if ROUND]
// 128x128 block, BK=32, 8 warps (2x4), warp tile 64x32, mma.m16n8k8.
// Operands rounded to tf32 at staging; inner loop = LDS + HMMA only.
// smem stride 36 -> A/B fragment loads are bank-conflict-free.
// ---------------------------------------------------------------------------
#define AS2 36
#define GEMM_SMEM (4 * 128 * AS2 * (int)sizeof(float))   // 73728 bytes

template<bool ROUND>
__global__ __launch_bounds__(256, 2) void gemm_mma(
    const float* __restrict__ A, const float* __restrict__ W,
    const float* __restrict__ bias, float scale, float* __restrict__ C)
{
    extern __shared__ float sm[];
    float* As = sm;                   // [2][128*AS2]
    float* Ws = sm + 2 * 128 * AS2;   // [2][128*AS2]

    const int m0 = blockIdx.y * 128;
    const int n0 = blockIdx.x * 128;
    const int t  = threadIdx.x;
    const int wid = t >> 5, lane = t & 31;
    const int g4 = lane >> 2, q4 = lane & 3;
    const int wm = wid >> 2;          // 0..1
    const int wn = wid & 3;           // 0..3
    const int lrow = t >> 1;          // 0..127
    const int lseg = (t & 1) * 16;

    float c[4][4][4];
    #pragma unroll
    for (int i = 0; i < 4; i++)
        #pragma unroll
        for (int j = 0; j < 4; j++)
            c[i][j][0] = c[i][j][1] = c[i][j][2] = c[i][j][3] = 0.f;

    const float* Ap = A + (size_t)(m0 + lrow) * D_MODEL + lseg;
    const float* Wp = W + (size_t)(n0 + lrow) * D_MODEL + lseg;

    // prologue: LDG tile 0
    float4 ra[4], rw[4];
    #pragma unroll
    for (int i = 0; i < 4; i++) {
        ra[i] = *(const float4*)(Ap + i * 4);
        rw[i] = *(const float4*)(Wp + i * 4);
    }

    const int NKT = D_MODEL / 32;
    for (int kt = 0; kt < NKT; kt++) {
        // STS tile kt (rounded to tf32) into buf kt&1
        float* Ab = As + (kt & 1) * 128 * AS2;
        float* Wb = Ws + (kt & 1) * 128 * AS2;
        #pragma unroll
        for (int i = 0; i < 4; i++) {
            float4 va = ra[i], vw = rw[i];
            va.x = __uint_as_float(f2tf(va.x)); va.y = __uint_as_float(f2tf(va.y));
            va.z = __uint_as_float(f2tf(va.z)); va.w = __uint_as_float(f2tf(va.w));
            vw.x = __uint_as_float(f2tf(vw.x)); vw.y = __uint_as_float(f2tf(vw.y));
            vw.z = __uint_as_float(f2tf(vw.z)); vw.w = __uint_as_float(f2tf(vw.w));
            *(float4*)&Ab[lrow * AS2 + lseg + i * 4] = va;
            *(float4*)&Wb[lrow * AS2 + lseg + i * 4] = vw;
        }
        __syncthreads();

        // LDG tile kt+1 (overlaps compute below)
        if (kt + 1 < NKT) {
            const int k0 = (kt + 1) * 32;
            #pragma unroll
            for (int i = 0; i < 4; i++) {
                ra[i] = *(const float4*)(Ap + k0 + i * 4);
                rw[i] = *(const float4*)(Wp + k0 + i * 4);
            }
        }

        // compute: 4 k8 steps
        const float* Aw = Ab + (wm * 64) * AS2;
        const float* Ww = Wb + (wn * 32) * AS2;
        #pragma unroll
        for (int kk = 0; kk < 4; kk++) {
            unsigned a[4][4];
            #pragma unroll
            for (int i = 0; i < 4; i++) {
                const float* ap = Aw + (i * 16 + g4) * AS2 + kk * 8 + q4;
                a[i][0] = __float_as_uint(ap[0]);
                a[i][1] = __float_as_uint(ap[8 * AS2]);
                a[i][2] = __float_as_uint(ap[4]);
                a[i][3] = __float_as_uint(ap[8 * AS2 + 4]);
            }
            #pragma unroll
            for (int j = 0; j < 4; j++) {
                const float* bp = Ww + (j * 8 + g4) * AS2 + kk * 8 + q4;
                unsigned b0 = __float_as_uint(bp[0]);
                unsigned b1 = __float_as_uint(bp[4]);
                #pragma unroll
                for (int i = 0; i < 4; i++)
                    mma8(c[i][j], a[i], b0, b1);
            }
        }
        // no trailing sync: next iter's STS targets the other buffer, whose
        // last readers were iter kt-1 (separated by this iter's sync).
    }

    // ---- epilogue: direct STG from fragments, bias in registers ----
    #pragma unroll
    for (int j = 0; j < 4; j++) {
        const int col = n0 + wn * 32 + j * 8 + 2 * q4;
        const float2 bb = *(const float2*)&bias[col];
        #pragma unroll
        for (int i = 0; i < 4; i++) {
            const int row = m0 + wm * 64 + i * 16 + g4;
            float2 v0, v1;
            v0.x = (c[i][j][0] + bb.x) * scale;
            v0.y = (c[i][j][1] + bb.y) * scale;
            v1.x = (c[i][j][2] + bb.x) * scale;
            v1.y = (c[i][j][3] + bb.y) * scale;
            if (ROUND) {
                v0.x = __uint_as_float(f2tf(v0.x));
                v0.y = __uint_as_float(f2tf(v0.y));
                v1.x = __uint_as_float(f2tf(v1.x));
                v1.y = __uint_as_float(f2tf(v1.y));
            }
            *(float2*)&C[(size_t)row * D_MODEL + col] = v0;
            *(float2*)&C[(size_t)(row + 8) * D_MODEL + col] = v1;
        }
    }
}

// ---------------------------------------------------------------------------
// Flash attention, mma.sync m16n8k8 tf32, register accumulators.
// Q/K/V arrive tf32-pre-rounded, so fragment loads are bit reinterprets.
// ---------------------------------------------------------------------------
#define KS 68
#define VS 72
#define PS 68
#define NTILES (SEQ / 64)
#define ATTN_SMEM ((128*PS + 2*64*KS + 2*64*VS) * (int)sizeof(float))  // 106496

__global__ __launch_bounds__(256, 2) void attn_mma(
    const float* __restrict__ Qb, const float* __restrict__ Kb,
    const float* __restrict__ Vb, float* __restrict__ Ob)
{
    extern __shared__ float sm[];
    float* Ps = sm;                         // [128][PS]  (Q staging, then P)
    float* Kbuf = Ps + 128 * PS;            // [2][64][KS]
    float* Vbuf = Kbuf + 2 * 64 * KS;       // [2][64][VS]

    const int qt = blockIdx.x, h = blockIdx.y, b = blockIdx.z;
    const int t = threadIdx.x, w = t >> 5, lane = t & 31;
    const int g4 = lane >> 2, q4 = lane & 3;
    const int base_q = b * SEQ + qt * 128;
    const int hcol = h * HEAD_DIM;

    // --- stage tile 0 of K/V via cp.async ---
    {
        const int base_k = b * SEQ;
        #pragma unroll
        for (int i = 0; i < 4; i++) {
            const int id = t + i * 256;
            const int row = id >> 4, seg = id & 15;
            const size_t g = (size_t)(base_k + row) * D_MODEL + hcol + seg * 4;
            cp_async16(&Kbuf[row * KS + seg * 4], Kb + g);
            cp_async16(&Vbuf[row * VS + seg * 4], Vb + g);
        }
    }
    CP_COMMIT();

    // --- stage Q and load A-fragments (already tf32 bit patterns) ---
    {
        const int r = t >> 1;
        const int c0 = (t & 1) * 32;
        #pragma unroll
        for (int i = 0; i < 8; i++)
            *(float4*)&Ps[r * PS + c0 + i * 4] =
                *(const float4*)&Qb[(size_t)(base_q + r) * D_MODEL + hcol + c0 + i * 4];
    }
    __syncwarp();

    unsigned qa[8][4];
    #pragma unroll
    for (int kk = 0; kk < 8; kk++) {
        qa[kk][0] = __float_as_uint(Ps[(w * 16 + g4)     * PS + kk * 8 + q4]);
        qa[kk][1] = __float_as_uint(Ps[(w * 16 + g4 + 8) * PS + kk * 8 + q4]);
        qa[kk][2] = __float_as_uint(Ps[(w * 16 + g4)     * PS + kk * 8 + q4 + 4]);
        qa[kk][3] = __float_as_uint(Ps[(w * 16 + g4 + 8) * PS + kk * 8 + q4 + 4]);
    }
    __syncwarp();   // Ps free for P reuse

    float of[8][4];
    #pragma unroll
    for (int n = 0; n < 8; n++)
        of[n][0] = of[n][1] = of[n][2] = of[n][3] = 0.f;
    float m0r = -1e30f, m1r = -1e30f, l0r = 0.f, l1r = 0.f;

    for (int jt = 0; jt < NTILES; jt++) {
        float* Kc = Kbuf + (jt & 1) * 64 * KS;
        float* Vc = Vbuf + (jt & 1) * 64 * VS;

        if (jt + 1 < NTILES) {
            float* Kn = Kbuf + ((jt + 1) & 1) * 64 * KS;
            float* Vn = Vbuf + ((jt + 1) & 1) * 64 * VS;
            const int base_k = b * SEQ + (jt + 1) * 64;
            #pragma unroll
            for (int i = 0; i < 4; i++) {
                const int id = t + i * 256;
                const int row = id >> 4, seg = id & 15;
                const size_t g = (size_t)(base_k + row) * D_MODEL + hcol + seg * 4;
                cp_async16(&Kn[row * KS + seg * 4], Kb + g);
                cp_async16(&Vn[row * VS + seg * 4], Vb + g);
            }
        }
        CP_COMMIT();
        CP_WAIT1();          // tile jt resident; jt+1 in flight
        __syncthreads();

        // ---- S = Q @ K^T ----
        float sfr[8][4];
        #pragma unroll
        for (int n = 0; n < 8; n++)
            sfr[n][0] = sfr[n][1] = sfr[n][2] = sfr[n][3] = 0.f;
        #pragma unroll
        for (int kk = 0; kk < 8; kk++) {
            #pragma unroll
            for (int n = 0; n < 8; n++) {
                const float* kp = &Kc[(n * 8 + g4) * KS + kk * 8 + q4];
                unsigned b0 = __float_as_uint(kp[0]);
                unsigned b1 = __float_as_uint(kp[4]);
                mma8(sfr[n], qa[kk], b0, b1);
            }
        }

        // ---- online softmax in registers ----
        float mx0 = -1e30f, mx1 = -1e30f;
        #pragma unroll
        for (int n = 0; n < 8; n++) {
            mx0 = fmaxf(mx0, fmaxf(sfr[n][0], sfr[n][1]));
            mx1 = fmaxf(mx1, fmaxf(sfr[n][2], sfr[n][3]));
        }
        mx0 = fmaxf(mx0, __shfl_xor_sync(0xffffffffu, mx0, 1));
        mx0 = fmaxf(mx0, __shfl_xor_sync(0xffffffffu, mx0, 2));
        mx1 = fmaxf(mx1, __shfl_xor_sync(0xffffffffu, mx1, 1));
        mx1 = fmaxf(mx1, __shfl_xor_sync(0xffffffffu, mx1, 2));

        const float mn0 = fmaxf(m0r, mx0);
        const float mn1 = fmaxf(m1r, mx1);
        const float a0 = __expf(m0r - mn0);
        const float a1 = __expf(m1r - mn1);
        m0r = mn0; m1r = mn1;

        float s0 = 0.f, s1 = 0.f;
        #pragma unroll
        for (int n = 0; n < 8; n++) {
            sfr[n][0] = __expf(sfr[n][0] - mn0);
            sfr[n][1] = __expf(sfr[n][1] - mn0);
            sfr[n][2] = __expf(sfr[n][2] - mn1);
            sfr[n][3] = __expf(sfr[n][3] - mn1);
            s0 += sfr[n][0] + sfr[n][1];
            s1 += sfr[n][2] + sfr[n][3];
            of[n][0] *= a0; of[n][1] *= a0;
            of[n][2] *= a1; of[n][3] *= a1;
            *(float2*)&Ps[(w * 16 + g4)     * PS + n * 8 + 2 * q4] =
                make_float2(sfr[n][0], sfr[n][1]);
            *(float2*)&Ps[(w * 16 + g4 + 8) * PS + n * 8 + 2 * q4] =
                make_float2(sfr[n][2], sfr[n][3]);
        }
        s0 += __shfl_xor_sync(0xffffffffu, s0, 1);
        s0 += __shfl_xor_sync(0xffffffffu, s0, 2);
        s1 += __shfl_xor_sync(0xffffffffu, s1, 1);
        s1 += __shfl_xor_sync(0xffffffffu, s1, 2);
        l0r = l0r * a0 + s0;
        l1r = l1r * a1 + s1;
        __syncwarp();

        // ---- O += P @ V ----
        #pragma unroll
        for (int kk = 0; kk < 8; kk++) {
            unsigned pa[4];
            pa[0] = f2tf(Ps[(w * 16 + g4)     * PS + kk * 8 + q4]);
            pa[1] = f2tf(Ps[(w * 16 + g4 + 8) * PS + kk * 8 + q4]);
            pa[2] = f2tf(Ps[(w * 16 + g4)     * PS + kk * 8 + q4 + 4]);
            pa[3] = f2tf(Ps[(w * 16 + g4 + 8) * PS + kk * 8 + q4 + 4]);
            #pragma unroll
            for (int n = 0; n < 8; n++) {
                unsigned b0 = __float_as_uint(Vc[(kk * 8 + q4)     * VS + n * 8 + g4]);
                unsigned b1 = __float_as_uint(Vc[(kk * 8 + q4 + 4) * VS + n * 8 + g4]);
                mma8(of[n], pa, b0, b1);
            }
        }
        __syncwarp();
        __syncthreads();   // all warps done with Kc/Vc before restaging
    }

    // ---- epilogue: normalize, write [B,T,H*hd] ----
    const float inv0 = 1.f / l0r;
    const float inv1 = 1.f / l1r;
    const int r0 = base_q + w * 16 + g4;
    #pragma unroll
    for (int n = 0; n < 8; n++) {
        const int c = hcol + n * 8 + 2 * q4;
        *(float2*)&Ob[(size_t)r0 * D_MODEL + c] =
            make_float2(of[n][0] * inv0, of[n][1] * inv0);
        *(float2*)&Ob[(size_t)(r0 + 8) * D_MODEL + c] =
            make_float2(of[n][2] * inv1, of[n][3] * inv1);
    }
}

// ---------------------------------------------------------------------------
extern "C" void kernel_launch(void* const* d_in, const int* in_sizes, int n_in,
                              void* d_out, int out_size)
{
    const float* query = (const float*)d_in[0];
    const float* key   = (const float*)d_in[1];
    const float* value = (const float*)d_in[2];
    const float* Wq    = (const float*)d_in[3];
    const float* bq    = (const float*)d_in[4];
    const float* Wk    = (const float*)d_in[5];
    const float* bk    = (const float*)d_in[6];
    const float* Wv    = (const float*)d_in[7];
    const float* bv    = (const float*)d_in[8];
    const float* Wo    = (const float*)d_in[9];
    const float* bo    = (const float*)d_in[10];
    float* out = (float*)d_out;

    float *pQ, *pK, *pV, *pA;
    cudaGetSymbolAddress((void**)&pQ, g_Q);
    cudaGetSymbolAddress((void**)&pK, g_K);
    cudaGetSymbolAddress((void**)&pV, g_V);
    cudaGetSymbolAddress((void**)&pA, g_Attn);

    cudaFuncSetAttribute(gemm_mma<true>,
                         cudaFuncAttributeMaxDynamicSharedMemorySize, GEMM_SMEM);
    cudaFuncSetAttribute(gemm_mma<false>,
                         cudaFuncAttributeMaxDynamicSharedMemorySize, GEMM_SMEM);
    cudaFuncSetAttribute(attn_mma,
                         cudaFuncAttributeMaxDynamicSharedMemorySize, ATTN_SMEM);

    dim3 gemm_grid(D_MODEL / 128, MTOT / 128);   // (8, 32)
    const float qscale = 0.125f;                 // 1/sqrt(64)

    gemm_mma<true><<<gemm_grid, 256, GEMM_SMEM>>>(query, Wq, bq, qscale, pQ);
    gemm_mma<true><<<gemm_grid, 256, GEMM_SMEM>>>(key,   Wk, bk, 1.f,    pK);
    gemm_mma<true><<<gemm_grid, 256, GEMM_SMEM>>>(value, Wv, bv, 1.f,    pV);

    dim3 attn_grid(SEQ / 128, NHEAD, BATCH);     // (16, 16, 2)
    attn_mma<<<attn_grid, 256, ATTN_SMEM>>>(pQ, pK, pV, pA);

    gemm_mma<false><<<gemm_grid, 256, GEMM_SMEM>>>(pA, Wo, bo, 1.f, out);
}